// round 13
// baseline (speedup 1.0000x reference)
#include <cuda_runtime.h>
#include <mma.h>
#include <math.h>

using namespace nvcuda;

// Problem constants
#define NB   2
#define NS   128
#define NROW (NB*NS)        // 256 rows (b*s)
#define NN   512            // feature dim
#define NM   1024           // 2*N output cols of GEMM
#define NK   512            // contraction dim

#define SAMPLE_ELEMS (NROW*NN)               // 131072
#define STD_ELEMS    ((long long)NROW*NN*NN) // 67108864

// TF32 GEMM tiling: CTA = 64x64, chunk K=32, split-K=2 -> 16 x 4 x 2 = 128 CTAs
#define BM 64
#define BN 64
#define CHUNK 32
#define KS 2
#define KPER (NK/KS)        // 256
#define NCHUNK (KPER/CHUNK) // 8
#define LDS_PAD 40          // smem row stride (floats)

// Scratch (no allocations allowed)
__device__ float g_part[KS * NROW * NM];   // 2 MB split-K partials
__device__ float g_var[NROW * NN];         // 0.5 MB softplus(var) buffer

// ---------------- TF32 tensor-core GEMM: C = A * W^T (split-K partials) -----
__global__ __launch_bounds__(256)
void gemm_kernel(const float* __restrict__ A, const float* __restrict__ W,
                 float* __restrict__ P) {
    __shared__ __align__(16) float As[BM][LDS_PAD];   // [m][k]
    __shared__ __align__(16) float Bs[BN][LDS_PAD];   // [n][k]

    const int tid  = threadIdx.x;
    const int warp = tid >> 5;

    const int bx = blockIdx.x & 15;         // N tile (0..15)
    const int by = (blockIdx.x >> 4) & 3;   // M tile (0..3)
    const int bz = blockIdx.x >> 6;         // K split (0..1)

    // Warp tiling: 4 (m) x 2 (n-pair) warps; each warp owns 16x32 of C
    const int m0 = (warp & 3) * 16;
    const int n0 = (warp >> 2) * 32;

    // Stage loads: thread t loads row t>>2, floats (t&3)*8 .. +7 (2x float4)
    const int srow = tid >> 2;
    const int scol = (tid & 3) * 8;
    const float* Ag = A + (size_t)(by * BM + srow) * NK + bz * KPER + scol;
    const float* Wg = W + (size_t)(bx * BN + srow) * NK + bz * KPER + scol;

    wmma::fragment<wmma::accumulator, 16, 16, 8, float> acc0, acc1;
    wmma::fill_fragment(acc0, 0.0f);
    wmma::fill_fragment(acc1, 0.0f);

    for (int c = 0; c < NCHUNK; c++) {
        // Prefetch this chunk from global into registers
        float4 a0 = *(const float4*)(Ag + c * CHUNK);
        float4 a1 = *(const float4*)(Ag + c * CHUNK + 4);
        float4 w0 = *(const float4*)(Wg + c * CHUNK);
        float4 w1 = *(const float4*)(Wg + c * CHUNK + 4);

        if (c > 0) __syncthreads();   // previous chunk's compute done
        *(float4*)&As[srow][scol]     = a0;
        *(float4*)&As[srow][scol + 4] = a1;
        *(float4*)&Bs[srow][scol]     = w0;
        *(float4*)&Bs[srow][scol + 4] = w1;
        __syncthreads();

        #pragma unroll
        for (int k8 = 0; k8 < CHUNK / 8; k8++) {
            wmma::fragment<wmma::matrix_a, 16, 16, 8, wmma::precision::tf32, wmma::row_major> fa;
            wmma::fragment<wmma::matrix_b, 16, 16, 8, wmma::precision::tf32, wmma::col_major> fb0, fb1;

            wmma::load_matrix_sync(fa, &As[m0][k8 * 8], LDS_PAD);
            #pragma unroll
            for (int q = 0; q < fa.num_elements; q++)
                fa.x[q] = wmma::__float_to_tf32(fa.x[q]);

            wmma::load_matrix_sync(fb0, &Bs[n0][k8 * 8], LDS_PAD);
            wmma::load_matrix_sync(fb1, &Bs[n0 + 16][k8 * 8], LDS_PAD);
            #pragma unroll
            for (int q = 0; q < fb0.num_elements; q++) {
                fb0.x[q] = wmma::__float_to_tf32(fb0.x[q]);
                fb1.x[q] = wmma::__float_to_tf32(fb1.x[q]);
            }

            wmma::mma_sync(acc0, fa, fb0, acc0);
            wmma::mma_sync(acc1, fa, fb1, acc1);
        }
    }

    // Epilogue: split-K partials
    float* Pp = P + (size_t)bz * (NROW * NM)
                  + (size_t)(by * BM + m0) * NM + bx * BN + n0;
    wmma::store_matrix_sync(Pp,      acc0, NM, wmma::mem_row_major);
    wmma::store_matrix_sync(Pp + 16, acc1, NM, wmma::mem_row_major);
}

// ---------------- Pointwise: reduce split-K + var/mu/sample (float2) --------
__device__ __forceinline__ float softplus_f(float x) {
    return fmaxf(x, 0.0f) + log1pf(expf(-fabsf(x)));
}

__global__ __launch_bounds__(256)
void pointwise_kernel(const float* __restrict__ P,
                      const float* __restrict__ bias,
                      const float* __restrict__ eps,
                      float2* __restrict__ out_sample,
                      float2* __restrict__ out_mu,
                      float2* __restrict__ var_buf) {
    int t = blockIdx.x * blockDim.x + threadIdx.x;   // 0 .. 65535 (float2 units)
    if (t >= SAMPLE_ELEMS / 2) return;
    int row = t >> 8;                 // /256 float2 per row
    int i2  = t & 255;                // float2 col index

    float2 sv = ((const float2*)bias)[i2];
    float2 sm = ((const float2*)bias)[(NN >> 1) + i2];
    #pragma unroll
    for (int z = 0; z < KS; z++) {
        const float2* Pz = (const float2*)(P + (size_t)z * (NROW * NM) + (size_t)row * NM);
        float2 pv = Pz[i2];
        float2 pm = Pz[(NN >> 1) + i2];
        sv.x += pv.x; sv.y += pv.y;
        sm.x += pm.x; sm.y += pm.y;
    }

    float2 var;
    var.x = softplus_f(sv.x);
    var.y = softplus_f(sv.y);

    float2 ep = ((const float2*)eps)[t];
    float2 smp;
    smp.x = fmaf(sqrtf(var.x), ep.x, sm.x);
    smp.y = fmaf(sqrtf(var.y), ep.y, sm.y);

    var_buf[t]    = var;
    out_mu[t]     = sm;
    out_sample[t] = smp;
}

// ---------------- Fill std_mat: zeros + diagonal in ONE streaming pass ------
__global__ __launch_bounds__(256)
void fill_std_kernel(const float* __restrict__ var_buf, float4* __restrict__ out4) {
    const long long total4 = STD_ELEMS >> 2;   // 16777216 float4
    long long idx = (long long)blockIdx.x * blockDim.x + threadIdx.x;
    const long long stride = (long long)gridDim.x * blockDim.x;
    for (; idx < total4; idx += stride) {
        long long j = idx << 2;                // float index
        int r  = (int)(j >> 9);                // global row (0 .. 131071)
        int cs = (int)(j & (NN - 1));          // col start of this float4
        int d  = (r & (NN - 1)) - cs;          // diag offset within this float4
        float4 v = make_float4(0.f, 0.f, 0.f, 0.f);
        if ((unsigned)d < 4u) {
            float vv = var_buf[r];
            if      (d == 0) v.x = vv;
            else if (d == 1) v.y = vv;
            else if (d == 2) v.z = vv;
            else             v.w = vv;
        }
        __stcs(&out4[idx], v);   // evict-streaming full-line stores
    }
}

extern "C" void kernel_launch(void* const* d_in, const int* in_sizes, int n_in,
                              void* d_out, int out_size) {
    const float* x   = (const float*)d_in[0];
    const float* W   = (const float*)d_in[1];
    const float* b   = (const float*)d_in[2];
    const float* eps = (const float*)d_in[3];

    float* out        = (float*)d_out;
    float* out_sample = out;
    float* out_mu     = out + SAMPLE_ELEMS;
    float* out_std    = out + 2 * SAMPLE_ELEMS;

    float* part;  cudaGetSymbolAddress((void**)&part, g_part);
    float* varb;  cudaGetSymbolAddress((void**)&varb, g_var);

    // 1) TF32 tensor-core GEMM -> partials (128 CTAs, split-K=2)
    gemm_kernel<<<16 * 4 * KS, 256>>>(x, W, part);

    // 2) Pointwise: reduce + sample/mu + var_buf (float2)
    pointwise_kernel<<<(SAMPLE_ELEMS / 2) / 256, 256>>>(part, b, eps,
                                                        (float2*)out_sample,
                                                        (float2*)out_mu,
                                                        (float2*)varb);

    // 3) Single-pass fill: zeros + diagonal (DRAM roofline stream)
    fill_std_kernel<<<8192, 256>>>(varb, (float4*)out_std);
}

// round 15
// speedup vs baseline: 1.0384x; 1.0384x over previous
#include <cuda_runtime.h>
#include <mma.h>
#include <math.h>

using namespace nvcuda;

// Problem constants
#define NB   2
#define NS   128
#define NROW (NB*NS)        // 256 rows (b*s)
#define NN   512            // feature dim
#define NM   1024           // 2*N output cols of GEMM
#define NK   512            // contraction dim

#define SAMPLE_ELEMS (NROW*NN)               // 131072
#define STD_ELEMS    ((long long)NROW*NN*NN) // 67108864

// TF32 GEMM tiling: CTA = 64x64, chunk K=32, split-K=4 -> 16 x 4 x 4 = 256 CTAs
#define BM 64
#define BN 64
#define CHUNK 32
#define KS 4
#define KPER (NK/KS)        // 128
#define NCHUNK (KPER/CHUNK) // 4
#define LDS_PAD 40          // smem row stride (floats)

// Scratch (no allocations allowed)
__device__ float g_part[KS * NROW * NM];   // 4 MB split-K partials
__device__ float g_var[NROW * NN];         // 0.5 MB softplus(var) buffer

// ---------------- TF32 tensor-core GEMM: C = A * W^T (split-K partials) -----
__global__ __launch_bounds__(256)
void gemm_kernel(const float* __restrict__ A, const float* __restrict__ W,
                 float* __restrict__ P) {
    __shared__ __align__(16) float As[BM][LDS_PAD];   // [m][k], tf32 values
    __shared__ __align__(16) float Bs[BN][LDS_PAD];   // [n][k], tf32 values

    const int tid  = threadIdx.x;
    const int warp = tid >> 5;

    const int bx = blockIdx.x & 15;         // N tile (0..15)
    const int by = (blockIdx.x >> 4) & 3;   // M tile (0..3)
    const int bz = blockIdx.x >> 6;         // K split (0..3)

    // Warp tiling: 4 (m) x 2 (n-pair) warps; each warp owns 16x32 of C
    const int m0 = (warp & 3) * 16;
    const int n0 = (warp >> 2) * 32;

    // Stage loads: thread t loads row t>>2, floats (t&3)*8 .. +7 (2x float4)
    const int srow = tid >> 2;
    const int scol = (tid & 3) * 8;
    const float* Ag = A + (size_t)(by * BM + srow) * NK + bz * KPER + scol;
    const float* Wg = W + (size_t)(bx * BN + srow) * NK + bz * KPER + scol;

    wmma::fragment<wmma::accumulator, 16, 16, 8, float> acc0, acc1;
    wmma::fill_fragment(acc0, 0.0f);
    wmma::fill_fragment(acc1, 0.0f);

    for (int c = 0; c < NCHUNK; c++) {
        // Prefetch this chunk from global into registers
        float4 a0 = *(const float4*)(Ag + c * CHUNK);
        float4 a1 = *(const float4*)(Ag + c * CHUNK + 4);
        float4 w0 = *(const float4*)(Wg + c * CHUNK);
        float4 w1 = *(const float4*)(Wg + c * CHUNK + 4);

        // Convert to tf32 in-register (truncation), so fragments need no fixup
        #pragma unroll
        for (int q = 0; q < 4; q++) {
            ((float*)&a0)[q] = wmma::__float_to_tf32(((float*)&a0)[q]);
            ((float*)&a1)[q] = wmma::__float_to_tf32(((float*)&a1)[q]);
            ((float*)&w0)[q] = wmma::__float_to_tf32(((float*)&w0)[q]);
            ((float*)&w1)[q] = wmma::__float_to_tf32(((float*)&w1)[q]);
        }

        if (c > 0) __syncthreads();   // previous chunk's compute done
        *(float4*)&As[srow][scol]     = a0;
        *(float4*)&As[srow][scol + 4] = a1;
        *(float4*)&Bs[srow][scol]     = w0;
        *(float4*)&Bs[srow][scol + 4] = w1;
        __syncthreads();

        #pragma unroll
        for (int k8 = 0; k8 < CHUNK / 8; k8++) {
            wmma::fragment<wmma::matrix_a, 16, 16, 8, wmma::precision::tf32, wmma::row_major> fa;
            wmma::fragment<wmma::matrix_b, 16, 16, 8, wmma::precision::tf32, wmma::col_major> fb0, fb1;

            wmma::load_matrix_sync(fa,  &As[m0][k8 * 8],      LDS_PAD);
            wmma::load_matrix_sync(fb0, &Bs[n0][k8 * 8],      LDS_PAD);
            wmma::load_matrix_sync(fb1, &Bs[n0 + 16][k8 * 8], LDS_PAD);

            wmma::mma_sync(acc0, fa, fb0, acc0);
            wmma::mma_sync(acc1, fa, fb1, acc1);
        }
    }

    // Epilogue: split-K partials
    float* Pp = P + (size_t)bz * (NROW * NM)
                  + (size_t)(by * BM + m0) * NM + bx * BN + n0;
    wmma::store_matrix_sync(Pp,      acc0, NM, wmma::mem_row_major);
    wmma::store_matrix_sync(Pp + 16, acc1, NM, wmma::mem_row_major);
}

// ---------------- Pointwise: reduce split-K + var/mu/sample (float2) --------
__device__ __forceinline__ float softplus_f(float x) {
    return fmaxf(x, 0.0f) + log1pf(expf(-fabsf(x)));
}

__global__ __launch_bounds__(256)
void pointwise_kernel(const float* __restrict__ P,
                      const float* __restrict__ bias,
                      const float* __restrict__ eps,
                      float2* __restrict__ out_sample,
                      float2* __restrict__ out_mu,
                      float2* __restrict__ var_buf) {
    int t = blockIdx.x * blockDim.x + threadIdx.x;   // 0 .. 65535 (float2 units)
    if (t >= SAMPLE_ELEMS / 2) return;
    int row = t >> 8;                 // /256 float2 per row
    int i2  = t & 255;                // float2 col index

    float2 sv = ((const float2*)bias)[i2];
    float2 sm = ((const float2*)bias)[(NN >> 1) + i2];
    #pragma unroll
    for (int z = 0; z < KS; z++) {
        const float2* Pz = (const float2*)(P + (size_t)z * (NROW * NM) + (size_t)row * NM);
        float2 pv = Pz[i2];
        float2 pm = Pz[(NN >> 1) + i2];
        sv.x += pv.x; sv.y += pv.y;
        sm.x += pm.x; sm.y += pm.y;
    }

    float2 var;
    var.x = softplus_f(sv.x);
    var.y = softplus_f(sv.y);

    float2 ep = ((const float2*)eps)[t];
    float2 smp;
    smp.x = fmaf(sqrtf(var.x), ep.x, sm.x);
    smp.y = fmaf(sqrtf(var.y), ep.y, sm.y);

    var_buf[t]    = var;
    out_mu[t]     = sm;
    out_sample[t] = smp;
}

// ---------------- Fill std_mat: zeros + diagonal in ONE streaming pass ------
__global__ __launch_bounds__(256)
void fill_std_kernel(const float* __restrict__ var_buf, float4* __restrict__ out4) {
    const long long total4 = STD_ELEMS >> 2;   // 16777216 float4
    long long idx = (long long)blockIdx.x * blockDim.x + threadIdx.x;
    const long long stride = (long long)gridDim.x * blockDim.x;
    for (; idx < total4; idx += stride) {
        long long j = idx << 2;                // float index
        int r  = (int)(j >> 9);                // global row (0 .. 131071)
        int cs = (int)(j & (NN - 1));          // col start of this float4
        int d  = (r & (NN - 1)) - cs;          // diag offset within this float4
        float4 v = make_float4(0.f, 0.f, 0.f, 0.f);
        if ((unsigned)d < 4u) {
            float vv = var_buf[r];
            if      (d == 0) v.x = vv;
            else if (d == 1) v.y = vv;
            else if (d == 2) v.z = vv;
            else             v.w = vv;
        }
        __stcs(&out4[idx], v);   // evict-streaming full-line stores
    }
}

extern "C" void kernel_launch(void* const* d_in, const int* in_sizes, int n_in,
                              void* d_out, int out_size) {
    const float* x   = (const float*)d_in[0];
    const float* W   = (const float*)d_in[1];
    const float* b   = (const float*)d_in[2];
    const float* eps = (const float*)d_in[3];

    float* out        = (float*)d_out;
    float* out_sample = out;
    float* out_mu     = out + SAMPLE_ELEMS;
    float* out_std    = out + 2 * SAMPLE_ELEMS;

    float* part;  cudaGetSymbolAddress((void**)&part, g_part);
    float* varb;  cudaGetSymbolAddress((void**)&varb, g_var);

    // 1) TF32 tensor-core GEMM -> partials (256 CTAs, split-K=4)
    gemm_kernel<<<16 * 4 * KS, 256>>>(x, W, part);

    // 2) Pointwise: reduce + sample/mu + var_buf (float2)
    pointwise_kernel<<<(SAMPLE_ELEMS / 2) / 256, 256>>>(part, b, eps,
                                                        (float2*)out_sample,
                                                        (float2*)out_mu,
                                                        (float2*)varb);

    // 3) Single-pass fill: zeros + diagonal (DRAM roofline stream)
    fill_std_kernel<<<8192, 256>>>(varb, (float4*)out_std);
}